// round 1
// baseline (speedup 1.0000x reference)
#include <cuda_runtime.h>
#include <cuda_bf16.h>
#include <cstdint>

// Problem constants
#define BB   4
#define CC   128
#define HH   128
#define WW   128
#define OO   256
#define KKK  9          // 3x3
#define KDIM 1152       // C*KK
#define HW   16384      // H*W

typedef unsigned long long ull;

// ---------------- scratch (no allocations allowed) ----------------
__device__ float g_xT[BB * HH * WW * CC];          // NHWC transposed x (33.5 MB)
__device__ float g_wT[KDIM * OO];                  // weight transposed [k][oc]
__device__ float g_w27[KDIM * 28];                 // combined offset+mod weights [k][28(pad)]
__device__ float g_posy[BB * HH * WW * KKK];
__device__ float g_posx[BB * HH * WW * KKK];
__device__ float g_mask[BB * HH * WW * KKK];

// ---------------- f32x2 helpers (sm_100+) ----------------
__device__ __forceinline__ ull pack2(float lo, float hi) {
    ull r; asm("mov.b64 %0, {%1, %2};" : "=l"(r) : "f"(lo), "f"(hi)); return r;
}
__device__ __forceinline__ float2 unpack2(ull v) {
    float2 r; asm("mov.b64 {%0, %1}, %2;" : "=f"(r.x), "=f"(r.y) : "l"(v)); return r;
}
__device__ __forceinline__ ull fma2(ull a, ull b, ull c) {
    ull d; asm("fma.rn.f32x2 %0, %1, %2, %3;" : "=l"(d) : "l"(a), "l"(b), "l"(c)); return d;
}

// ---------------- K0: NCHW -> NHWC transpose of x ----------------
__global__ void k_tx(const float* __restrict__ x) {
    __shared__ float t[32][33];
    int b  = blockIdx.z;
    int c0 = blockIdx.y * 32;
    int p0 = blockIdx.x * 32;
    int tx = threadIdx.x, ty = threadIdx.y;
#pragma unroll
    for (int i = 0; i < 32; i += 8)
        t[ty + i][tx] = x[(size_t)(b * CC + c0 + ty + i) * HW + p0 + tx];
    __syncthreads();
#pragma unroll
    for (int i = 0; i < 32; i += 8)
        g_xT[(size_t)(b * HW + p0 + ty + i) * CC + c0 + tx] = t[tx][ty + i];
}

// ---------------- K0b: weight prep ----------------
__global__ void k_prep(const float* __restrict__ ow, const float* __restrict__ mw,
                       const float* __restrict__ w) {
    int stride = gridDim.x * blockDim.x;
    for (int i = blockIdx.x * blockDim.x + threadIdx.x; i < KDIM * OO; i += stride) {
        int k = i >> 8; int oc = i & 255;
        g_wT[i] = w[oc * KDIM + k];
    }
    for (int i = blockIdx.x * blockDim.x + threadIdx.x; i < KDIM * 28; i += stride) {
        int k = i / 28; int oc = i - k * 28;
        float v = 0.f;
        if (oc < 18)      v = ow[oc * KDIM + k];
        else if (oc < 27) v = mw[(oc - 18) * KDIM + k];
        g_w27[i] = v;
    }
}

// ---------------- K1: offset/modulator conv -> positions & mask ----------------
// block = 128 threads (one per wo), grid = B*H (one row per block)
__global__ void __launch_bounds__(128) k_stage1(const float* __restrict__ x,
                                                const float* __restrict__ ob,
                                                const float* __restrict__ mb) {
    __shared__ float xs[8 * 3 * 130];            // [ci][r][j], j = wx+1
    __shared__ __align__(16) float ws[8 * 9 * 28];
    int bi = blockIdx.x;
    int b  = bi >> 7;
    int ho = bi & 127;
    int wo = threadIdx.x;

    ull acc[14];
#pragma unroll
    for (int j = 0; j < 14; j++) acc[j] = pack2(0.f, 0.f);

    for (int cc = 0; cc < CC; cc += 8) {
        __syncthreads();
        for (int i = threadIdx.x; i < 2016; i += 128)
            ws[i] = g_w27[cc * 9 * 28 + i];
        for (int i = threadIdx.x; i < 3120; i += 128) {
            int ci = i / 390; int rem = i - ci * 390;
            int r = rem / 130; int j = rem - r * 130;
            int hy = ho - 1 + r; int wx = j - 1;
            float v = 0.f;
            if ((unsigned)hy < 128u && (unsigned)wx < 128u)
                v = x[(size_t)((b * CC + cc + ci) * HH + hy) * WW + wx];
            xs[i] = v;
        }
        __syncthreads();

        for (int ci = 0; ci < 8; ci++) {
            float xv[9];
#pragma unroll
            for (int r = 0; r < 3; r++)
#pragma unroll
                for (int kx = 0; kx < 3; kx++)
                    xv[r * 3 + kx] = xs[ci * 390 + r * 130 + wo + kx];
#pragma unroll
            for (int kk = 0; kk < 9; kk++) {
                ull xd = pack2(xv[kk], xv[kk]);
                const ulonglong2* wr = (const ulonglong2*)(ws + (ci * 9 + kk) * 28);
#pragma unroll
                for (int j = 0; j < 7; j++) {
                    ulonglong2 wp = wr[j];
                    acc[2 * j]     = fma2(wp.x, xd, acc[2 * j]);
                    acc[2 * j + 1] = fma2(wp.y, xd, acc[2 * j + 1]);
                }
            }
        }
    }

    float v27[28];
#pragma unroll
    for (int j = 0; j < 14; j++) {
        float2 p = unpack2(acc[j]);
        v27[2 * j] = p.x; v27[2 * j + 1] = p.y;
    }

    int pixbase = ((b * HH + ho) * WW + wo) * KKK;
#pragma unroll
    for (int kk = 0; kk < 9; kk++) {
        int ky = kk / 3, kx = kk % 3;
        float offy = v27[2 * kk]     + ob[2 * kk];
        float offx = v27[2 * kk + 1] + ob[2 * kk + 1];
        float mm   = v27[18 + kk]    + mb[kk];
        mm = 2.0f / (1.0f + expf(-mm));
        g_posy[pixbase + kk] = (float)(ho - 1 + ky) + offy;
        g_posx[pixbase + kk] = (float)(wo - 1 + kx) + offx;
        g_mask[pixbase + kk] = mm;
    }
}

// ---------------- K2: deformable gather + GEMM ----------------
// block = 256 threads, M-tile = 16 pixels (one (b,ho) row segment), N = 256, K = 1152
#define KC 32
#define SMEM_BYTES ((18432 + KC * 256) * 4 + 144 * 32)

__global__ void __launch_bounds__(256, 2) k_stage2(float* __restrict__ out) {
    extern __shared__ float smem[];
    float* col = smem;                       // [1152][16]
    float* ws  = smem + 18432;               // [KC][256]
    int4*   sIdx = (int4*)(smem + 18432 + KC * 256);
    float4* sW   = (float4*)((char*)sIdx + 144 * 16);

    int bi  = blockIdx.x;
    int b   = bi >> 10;
    int ho  = (bi >> 3) & 127;
    int wo0 = (bi & 7) << 4;
    int tid = threadIdx.x;

    // ---- phase 0: per-(m,kk) tap indices + premultiplied weights ----
    if (tid < 144) {
        int m = tid / 9, kk = tid - (tid / 9) * 9;
        int wo = wo0 + m;
        int pix = ((b * HH + ho) * WW + wo) * KKK + kk;
        float py = g_posy[pix], px = g_posx[pix], mk = g_mask[pix];
        float y0f = floorf(py), x0f = floorf(px);
        float wy = py - y0f, wx = px - x0f;
        int iy0 = (int)y0f, ix0 = (int)x0f;
        int iy1 = iy0 + 1,  ix1 = ix0 + 1;
        bool vy0 = (unsigned)iy0 < 128u, vy1 = (unsigned)iy1 < 128u;
        bool vx0 = (unsigned)ix0 < 128u, vx1 = (unsigned)ix1 < 128u;
        int cy0 = min(max(iy0, 0), 127), cy1 = min(max(iy1, 0), 127);
        int cx0 = min(max(ix0, 0), 127), cx1 = min(max(ix1, 0), 127);
        float w00 = mk * (1.f - wy) * (1.f - wx) * ((vy0 && vx0) ? 1.f : 0.f);
        float w01 = mk * (1.f - wy) * wx         * ((vy0 && vx1) ? 1.f : 0.f);
        float w10 = mk * wy * (1.f - wx)         * ((vy1 && vx0) ? 1.f : 0.f);
        float w11 = mk * wy * wx                 * ((vy1 && vx1) ? 1.f : 0.f);
        sIdx[tid] = make_int4(((b * HH + cy0) * WW + cx0) * CC,
                              ((b * HH + cy0) * WW + cx1) * CC,
                              ((b * HH + cy1) * WW + cx0) * CC,
                              ((b * HH + cy1) * WW + cx1) * CC);
        sW[tid] = make_float4(w00, w01, w10, w11);
    }
    __syncthreads();

    // ---- phase 1: gather into col[k][m], k = c*9+kk ----
    for (int t = tid; t < 1152; t += 256) {
        int mk  = t >> 3;
        int oct = t & 7;
        int c0  = oct * 16;
        int m  = mk / 9, kk = mk - m * 9;
        int4   ti = sIdx[mk];
        float4 tw = sW[mk];
        const float4* P0 = (const float4*)(g_xT + ti.x + c0);
        const float4* P1 = (const float4*)(g_xT + ti.y + c0);
        const float4* P2 = (const float4*)(g_xT + ti.z + c0);
        const float4* P3 = (const float4*)(g_xT + ti.w + c0);
        float* cw = col + kk * 16 + m;
#pragma unroll
        for (int q = 0; q < 4; q++) {
            float4 a = P0[q], e = P1[q], f = P2[q], g = P3[q];
            float4 r;
            r.x = fmaf(g.x, tw.w, fmaf(f.x, tw.z, fmaf(e.x, tw.y, a.x * tw.x)));
            r.y = fmaf(g.y, tw.w, fmaf(f.y, tw.z, fmaf(e.y, tw.y, a.y * tw.x)));
            r.z = fmaf(g.z, tw.w, fmaf(f.z, tw.z, fmaf(e.z, tw.y, a.z * tw.x)));
            r.w = fmaf(g.w, tw.w, fmaf(f.w, tw.z, fmaf(e.w, tw.y, a.w * tw.x)));
            int c = c0 + q * 4;
            cw[(c + 0) * 144] = r.x;
            cw[(c + 1) * 144] = r.y;
            cw[(c + 2) * 144] = r.z;
            cw[(c + 3) * 144] = r.w;
        }
    }

    // ---- phase 2: GEMM, thread = one oc, 16 pixels in f32x2 pairs ----
    int oc = tid;
    ull acc[8];
#pragma unroll
    for (int j = 0; j < 8; j++) acc[j] = pack2(0.f, 0.f);

    for (int kc = 0; kc < KDIM; kc += KC) {
        __syncthreads();
        {
            const float4* src = (const float4*)(g_wT + kc * 256);
            float4* dst = (float4*)ws;
            for (int i = tid; i < (KC * 256) / 4; i += 256) dst[i] = src[i];
        }
        __syncthreads();
#pragma unroll 4
        for (int kl = 0; kl < KC; kl++) {
            float w = ws[kl * 256 + oc];
            ull w2 = pack2(w, w);
            const ulonglong2* cp = (const ulonglong2*)(col + (kc + kl) * 16);
            ulonglong2 a = cp[0], b2 = cp[1], c2 = cp[2], d2 = cp[3];
            acc[0] = fma2(a.x,  w2, acc[0]);
            acc[1] = fma2(a.y,  w2, acc[1]);
            acc[2] = fma2(b2.x, w2, acc[2]);
            acc[3] = fma2(b2.y, w2, acc[3]);
            acc[4] = fma2(c2.x, w2, acc[4]);
            acc[5] = fma2(c2.y, w2, acc[5]);
            acc[6] = fma2(d2.x, w2, acc[6]);
            acc[7] = fma2(d2.y, w2, acc[7]);
        }
    }

    // ---- epilogue: transpose through smem for coalesced stores ----
    __syncthreads();
    float* so = col;  // reuse (needs 4096 floats)
#pragma unroll
    for (int j = 0; j < 8; j++) {
        float2 p = unpack2(acc[j]);
        so[oc * 16 + 2 * j]     = p.x;
        so[oc * 16 + 2 * j + 1] = p.y;
    }
    __syncthreads();
    size_t obase = (size_t)b * OO * HW + (size_t)ho * WW + wo0;
    for (int i = tid; i < 4096; i += 256) {
        int o2 = i >> 4, m = i & 15;
        out[obase + (size_t)o2 * HW + m] = so[i];
    }
}

// ---------------- host launcher ----------------
extern "C" void kernel_launch(void* const* d_in, const int* in_sizes, int n_in,
                              void* d_out, int out_size) {
    (void)in_sizes; (void)n_in; (void)out_size;
    const float* x  = (const float*)d_in[0];
    const float* ow = (const float*)d_in[1];
    const float* ob = (const float*)d_in[2];
    const float* mw = (const float*)d_in[3];
    const float* mb = (const float*)d_in[4];
    const float* w  = (const float*)d_in[5];
    float* out = (float*)d_out;

    cudaFuncSetAttribute(k_stage2, cudaFuncAttributeMaxDynamicSharedMemorySize, SMEM_BYTES);

    k_tx<<<dim3(HW / 32, CC / 32, BB), dim3(32, 8)>>>(x);
    k_prep<<<512, 256>>>(ow, mw, w);
    k_stage1<<<BB * HH, 128>>>(x, ob, mb);
    k_stage2<<<BB * HH * (WW / 16), 256, SMEM_BYTES>>>(out);
}

// round 2
// speedup vs baseline: 1.4389x; 1.4389x over previous
#include <cuda_runtime.h>
#include <cuda_bf16.h>
#include <cstdint>

// Problem constants
#define BB   4
#define CC   128
#define HH   128
#define WW   128
#define OO   256
#define KKK  9          // 3x3
#define KDIM 1152       // C*KK
#define HW   16384      // H*W

typedef unsigned long long ull;

// ---------------- scratch (no allocations allowed) ----------------
__device__ float g_xT[BB * HH * WW * CC];          // NHWC transposed x (33.5 MB)
__device__ float g_wT[KDIM * OO];                  // weight transposed [k][oc]
__device__ float g_w27[KDIM * 28];                 // combined offset+mod weights [k][28(pad)]
__device__ float g_posy[BB * HH * WW * KKK];
__device__ float g_posx[BB * HH * WW * KKK];
__device__ float g_mask[BB * HH * WW * KKK];

// ---------------- f32x2 helpers (sm_100+) ----------------
__device__ __forceinline__ ull pack2(float lo, float hi) {
    ull r; asm("mov.b64 %0, {%1, %2};" : "=l"(r) : "f"(lo), "f"(hi)); return r;
}
__device__ __forceinline__ float2 unpack2(ull v) {
    float2 r; asm("mov.b64 {%0, %1}, %2;" : "=f"(r.x), "=f"(r.y) : "l"(v)); return r;
}
__device__ __forceinline__ ull fma2(ull a, ull b, ull c) {
    ull d; asm("fma.rn.f32x2 %0, %1, %2, %3;" : "=l"(d) : "l"(a), "l"(b), "l"(c)); return d;
}

// ---------------- K0: NCHW -> NHWC transpose of x ----------------
__global__ void k_tx(const float* __restrict__ x) {
    __shared__ float t[32][33];
    int b  = blockIdx.z;
    int c0 = blockIdx.y * 32;
    int p0 = blockIdx.x * 32;
    int tx = threadIdx.x, ty = threadIdx.y;
#pragma unroll
    for (int i = 0; i < 32; i += 8)
        t[ty + i][tx] = x[(size_t)(b * CC + c0 + ty + i) * HW + p0 + tx];
    __syncthreads();
#pragma unroll
    for (int i = 0; i < 32; i += 8)
        g_xT[(size_t)(b * HW + p0 + ty + i) * CC + c0 + tx] = t[tx][ty + i];
}

// ---------------- K0b: weight prep ----------------
__global__ void k_prep(const float* __restrict__ ow, const float* __restrict__ mw,
                       const float* __restrict__ w) {
    int stride = gridDim.x * blockDim.x;
    for (int i = blockIdx.x * blockDim.x + threadIdx.x; i < KDIM * OO; i += stride) {
        int k = i >> 8; int oc = i & 255;
        g_wT[i] = w[oc * KDIM + k];
    }
    for (int i = blockIdx.x * blockDim.x + threadIdx.x; i < KDIM * 28; i += stride) {
        int k = i / 28; int oc = i - k * 28;
        float v = 0.f;
        if (oc < 18)      v = ow[oc * KDIM + k];
        else if (oc < 27) v = mw[(oc - 18) * KDIM + k];
        g_w27[i] = v;
    }
}

// ---------------- K1: offset/modulator conv -> positions & mask ----------------
__global__ void __launch_bounds__(128) k_stage1(const float* __restrict__ x,
                                                const float* __restrict__ ob,
                                                const float* __restrict__ mb) {
    __shared__ float xs[8 * 3 * 130];            // [ci][r][j], j = wx+1
    __shared__ __align__(16) float ws[8 * 9 * 28];
    int bi = blockIdx.x;
    int b  = bi >> 7;
    int ho = bi & 127;
    int wo = threadIdx.x;

    ull acc[14];
#pragma unroll
    for (int j = 0; j < 14; j++) acc[j] = pack2(0.f, 0.f);

    for (int cc = 0; cc < CC; cc += 8) {
        __syncthreads();
        for (int i = threadIdx.x; i < 2016; i += 128)
            ws[i] = g_w27[cc * 9 * 28 + i];
        for (int i = threadIdx.x; i < 3120; i += 128) {
            int ci = i / 390; int rem = i - ci * 390;
            int r = rem / 130; int j = rem - r * 130;
            int hy = ho - 1 + r; int wx = j - 1;
            float v = 0.f;
            if ((unsigned)hy < 128u && (unsigned)wx < 128u)
                v = x[(size_t)((b * CC + cc + ci) * HH + hy) * WW + wx];
            xs[i] = v;
        }
        __syncthreads();

        for (int ci = 0; ci < 8; ci++) {
            float xv[9];
#pragma unroll
            for (int r = 0; r < 3; r++)
#pragma unroll
                for (int kx = 0; kx < 3; kx++)
                    xv[r * 3 + kx] = xs[ci * 390 + r * 130 + wo + kx];
#pragma unroll
            for (int kk = 0; kk < 9; kk++) {
                ull xd = pack2(xv[kk], xv[kk]);
                const ulonglong2* wr = (const ulonglong2*)(ws + (ci * 9 + kk) * 28);
#pragma unroll
                for (int j = 0; j < 7; j++) {
                    ulonglong2 wp = wr[j];
                    acc[2 * j]     = fma2(wp.x, xd, acc[2 * j]);
                    acc[2 * j + 1] = fma2(wp.y, xd, acc[2 * j + 1]);
                }
            }
        }
    }

    float v27[28];
#pragma unroll
    for (int j = 0; j < 14; j++) {
        float2 p = unpack2(acc[j]);
        v27[2 * j] = p.x; v27[2 * j + 1] = p.y;
    }

    int pixbase = ((b * HH + ho) * WW + wo) * KKK;
#pragma unroll
    for (int kk = 0; kk < 9; kk++) {
        int ky = kk / 3, kx = kk % 3;
        float offy = v27[2 * kk]     + ob[2 * kk];
        float offx = v27[2 * kk + 1] + ob[2 * kk + 1];
        float mm   = v27[18 + kk]    + mb[kk];
        mm = 2.0f / (1.0f + expf(-mm));
        g_posy[pixbase + kk] = (float)(ho - 1 + ky) + offy;
        g_posx[pixbase + kk] = (float)(wo - 1 + kx) + offx;
        g_mask[pixbase + kk] = mm;
    }
}

// ---------------- K2: deformable gather + register-blocked GEMM ----------------
// block = 256 threads, M-tile = 32 pixels, N = 256, K = 1152, thread tile 4m x 8oc
#define MT    32
#define CS    36                      // col row stride (padded, 16B-aligned)
#define KC    32                      // weight chunk
#define COL_F (KDIM * CS)             // 41472 floats
#define WS_F  (KC * 256)              // 8192 floats
#define NTAP  (MT * KKK)              // 288
#define SMEM_BYTES ((COL_F + WS_F) * 4 + NTAP * 32)

__global__ void __launch_bounds__(256, 1) k_stage2(float* __restrict__ out) {
    extern __shared__ float smem[];
    float* col = smem;                          // [1152][36]
    float* ws  = smem + COL_F;                  // [KC][256]
    int4*   sIdx = (int4*)(smem + COL_F + WS_F);
    float4* sW   = (float4*)((char*)sIdx + NTAP * 16);

    int bi  = blockIdx.x;
    int b   = bi >> 9;
    int ho  = (bi >> 2) & 127;
    int wo0 = (bi & 3) << 5;
    int tid = threadIdx.x;

    // ---- phase 0: per-(m,kk) tap indices + premultiplied bilinear weights ----
    for (int tap = tid; tap < NTAP; tap += 256) {
        int m = tap / 9, kk = tap - m * 9;
        int wo = wo0 + m;
        int pix = ((b * HH + ho) * WW + wo) * KKK + kk;
        float py = g_posy[pix], px = g_posx[pix], mk = g_mask[pix];
        float y0f = floorf(py), x0f = floorf(px);
        float wy = py - y0f, wx = px - x0f;
        int iy0 = (int)y0f, ix0 = (int)x0f;
        int iy1 = iy0 + 1,  ix1 = ix0 + 1;
        bool vy0 = (unsigned)iy0 < 128u, vy1 = (unsigned)iy1 < 128u;
        bool vx0 = (unsigned)ix0 < 128u, vx1 = (unsigned)ix1 < 128u;
        int cy0 = min(max(iy0, 0), 127), cy1 = min(max(iy1, 0), 127);
        int cx0 = min(max(ix0, 0), 127), cx1 = min(max(ix1, 0), 127);
        float w00 = mk * (1.f - wy) * (1.f - wx) * ((vy0 && vx0) ? 1.f : 0.f);
        float w01 = mk * (1.f - wy) * wx         * ((vy0 && vx1) ? 1.f : 0.f);
        float w10 = mk * wy * (1.f - wx)         * ((vy1 && vx0) ? 1.f : 0.f);
        float w11 = mk * wy * wx                 * ((vy1 && vx1) ? 1.f : 0.f);
        sIdx[tap] = make_int4(((b * HH + cy0) * WW + cx0) * CC,
                              ((b * HH + cy0) * WW + cx1) * CC,
                              ((b * HH + cy1) * WW + cx0) * CC,
                              ((b * HH + cy1) * WW + cx1) * CC);
        sW[tap] = make_float4(w00, w01, w10, w11);
    }
    __syncthreads();

    // ---- phase 1: gather into col[k][m], k = c*9+kk ----
    for (int it = tid; it < NTAP * 8; it += 256) {
        int tap = it >> 3;
        int oct = it & 7;
        int c0  = oct << 4;             // 16 channels per item
        int m = tap / 9, kk = tap - (tap / 9) * 9;
        int4   ti = sIdx[tap];
        float4 tw = sW[tap];
        const float4* P0 = (const float4*)(g_xT + ti.x + c0);
        const float4* P1 = (const float4*)(g_xT + ti.y + c0);
        const float4* P2 = (const float4*)(g_xT + ti.z + c0);
        const float4* P3 = (const float4*)(g_xT + ti.w + c0);
        float* cw = col + (c0 * 9 + kk) * CS + m;   // k0 = c0*9+kk
#pragma unroll
        for (int q = 0; q < 4; q++) {
            float4 a = P0[q], e = P1[q], f = P2[q], g = P3[q];
            float4 r;
            r.x = fmaf(g.x, tw.w, fmaf(f.x, tw.z, fmaf(e.x, tw.y, a.x * tw.x)));
            r.y = fmaf(g.y, tw.w, fmaf(f.y, tw.z, fmaf(e.y, tw.y, a.y * tw.x)));
            r.z = fmaf(g.z, tw.w, fmaf(f.z, tw.z, fmaf(e.z, tw.y, a.z * tw.x)));
            r.w = fmaf(g.w, tw.w, fmaf(f.w, tw.z, fmaf(e.w, tw.y, a.w * tw.x)));
            // c = c0 + 4q + j  ->  k advances by 9 per channel -> 9*CS floats
            float* cq = cw + (4 * q) * 9 * CS;
            cq[0 * 9 * CS] = r.x;
            cq[1 * 9 * CS] = r.y;
            cq[2 * 9 * CS] = r.z;
            cq[3 * 9 * CS] = r.w;
        }
    }

    // ---- phase 2: GEMM, thread tile 4m x 8oc ----
    int tn  = tid >> 3;          // 0..31 -> oc0 = tn*8
    int tm  = tid & 7;           // 0..7  -> m0 = tm*4
    int oc0 = tn << 3;
    int m4  = tm << 2;

    ull acc[16];
#pragma unroll
    for (int j = 0; j < 16; j++) acc[j] = pack2(0.f, 0.f);

    // preload chunk 0 of weights into registers
    float4 pre[8];
    {
        const float4* src = (const float4*)g_wT;
#pragma unroll
        for (int j = 0; j < 8; j++) pre[j] = src[tid + 256 * j];
    }

    for (int kc = 0; kc < KDIM; kc += KC) {
        __syncthreads();                    // prev chunk consumed / col ready
        {
            float4* dst = (float4*)ws;
#pragma unroll
            for (int j = 0; j < 8; j++) dst[tid + 256 * j] = pre[j];
        }
        __syncthreads();
        if (kc + KC < KDIM) {
            const float4* src = (const float4*)(g_wT + (kc + KC) * 256);
#pragma unroll
            for (int j = 0; j < 8; j++) pre[j] = src[tid + 256 * j];
        }
#pragma unroll 4
        for (int kl = 0; kl < KC; kl++) {
            float4 cv = *(const float4*)(col + (kc + kl) * CS + m4);
            const ull* wrow = (const ull*)(ws + (kl << 8) + oc0);
            ull w0 = wrow[0], w1 = wrow[1], w2 = wrow[2], w3 = wrow[3];
            ull cm;
            cm = pack2(cv.x, cv.x);
            acc[0]  = fma2(w0, cm, acc[0]);  acc[1]  = fma2(w1, cm, acc[1]);
            acc[2]  = fma2(w2, cm, acc[2]);  acc[3]  = fma2(w3, cm, acc[3]);
            cm = pack2(cv.y, cv.y);
            acc[4]  = fma2(w0, cm, acc[4]);  acc[5]  = fma2(w1, cm, acc[5]);
            acc[6]  = fma2(w2, cm, acc[6]);  acc[7]  = fma2(w3, cm, acc[7]);
            cm = pack2(cv.z, cv.z);
            acc[8]  = fma2(w0, cm, acc[8]);  acc[9]  = fma2(w1, cm, acc[9]);
            acc[10] = fma2(w2, cm, acc[10]); acc[11] = fma2(w3, cm, acc[11]);
            cm = pack2(cv.w, cv.w);
            acc[12] = fma2(w0, cm, acc[12]); acc[13] = fma2(w1, cm, acc[13]);
            acc[14] = fma2(w2, cm, acc[14]); acc[15] = fma2(w3, cm, acc[15]);
        }
    }

    // ---- epilogue: transpose through smem for coalesced stores ----
    __syncthreads();
    float* so = col;                 // reuse: needs 256*33 = 8448 floats
#pragma unroll
    for (int mi = 0; mi < 4; mi++) {
        int m = m4 + mi;
#pragma unroll
        for (int oj = 0; oj < 4; oj++) {
            float2 p = unpack2(acc[mi * 4 + oj]);
            so[(oc0 + 2 * oj)     * 33 + m] = p.x;
            so[(oc0 + 2 * oj + 1) * 33 + m] = p.y;
        }
    }
    __syncthreads();
    size_t obase = (size_t)b * OO * HW + (size_t)ho * WW + wo0;
    for (int t = 0; t < 32; t++) {
        int idx = tid + 256 * t;
        int oc = idx >> 5, mm = idx & 31;
        out[obase + (size_t)oc * HW + mm] = so[oc * 33 + mm];
    }
}

// ---------------- host launcher ----------------
extern "C" void kernel_launch(void* const* d_in, const int* in_sizes, int n_in,
                              void* d_out, int out_size) {
    (void)in_sizes; (void)n_in; (void)out_size;
    const float* x  = (const float*)d_in[0];
    const float* ow = (const float*)d_in[1];
    const float* ob = (const float*)d_in[2];
    const float* mw = (const float*)d_in[3];
    const float* mb = (const float*)d_in[4];
    const float* w  = (const float*)d_in[5];
    float* out = (float*)d_out;

    cudaFuncSetAttribute(k_stage2, cudaFuncAttributeMaxDynamicSharedMemorySize, SMEM_BYTES);

    k_tx<<<dim3(HW / 32, CC / 32, BB), dim3(32, 8)>>>(x);
    k_prep<<<512, 256>>>(ow, mw, w);
    k_stage1<<<BB * HH, 128>>>(x, ob, mb);
    k_stage2<<<BB * HH * (WW / 32), 256, SMEM_BYTES>>>(out);
}